// round 13
// baseline (speedup 1.0000x reference)
#include <cuda_runtime.h>
#include <cuda_bf16.h>

// VolumeSDFRenderer: R=65536 rays, N=128 samples.
// inputs: distance [R,N] f32, color [R,N,3] f32, depth_values [R,N] f32
// output: concat(out_color [R,3], geometry zeros [R,N,3]) f32.
//
// TWO RAYS PER WARP, two phases per ray, fully interleaved for ILP:
//  - both rays' phase-1 distance/depth loads issue up front (4 indep LDGs)
//  - the two warp scans run in one fused shuffle loop (indep dep-chains)
//  - per-lane color cull (prefix > -ln(3e-4)) and warp-uniform phase-2 tail
//    cull (half-ray cumsum > -ln(3e-4)) as calibrated in R9-R11
//    (rel_err scales linearly with T_EPS; 3e-4 -> measured ~2.2e-4)
//  - adjacent rays' geometry slabs form one contiguous 192-float4 zero region
// R11 lesson: tail cull saved ~20MB but serialized the warp (phase-2 loads
// behind scan broadcast) -> latency-bound. Interleaving 2 rays restores
// independent work at every stall point.

#define ALPHA 10.0f
#define INV_BETA 20.0f      // 1/0.05
#define FAR_DELTA 1e10f
#define CULL_LOG 8.112f     // -ln(3e-4)

__device__ __forceinline__ float sdf_density(float dist) {
    float s = -dist;
    float e = __expf(-INV_BETA * fabsf(s));
    return (s <= 0.0f) ? (0.5f * ALPHA * e) : (ALPHA - 0.5f * ALPHA * e);
}

__global__ __launch_bounds__(256)
void volume_sdf_fused_kernel(const float* __restrict__ distance,
                             const float* __restrict__ color,
                             const float* __restrict__ depth,
                             float* __restrict__ out,
                             int n_rays)
{
    const int warp_id = (blockIdx.x * blockDim.x + threadIdx.x) >> 5;
    const int lane    = threadIdx.x & 31;
    const int ray0 = warp_id * 2;
    if (ray0 >= n_rays) return;
    const int ray1 = ray0 + 1;

    const size_t b0 = (size_t)ray0 * 128;
    const size_t b1 = (size_t)ray1 * 128;

    // ---- front-batched phase-1 loads for BOTH rays (4 indep float2 LDGs) ----
    const float2 dA0 = reinterpret_cast<const float2*>(distance + b0)[lane];
    const float2 tA0 = reinterpret_cast<const float2*>(depth    + b0)[lane];
    const float2 dA1 = reinterpret_cast<const float2*>(distance + b1)[lane];
    const float2 tA1 = reinterpret_cast<const float2*>(depth    + b1)[lane];
    const float  t64_0 = depth[b0 + 64];
    const float  t64_1 = depth[b1 + 64];

    // ---- zero both rays' geometry: 768 floats = 192 float4, contiguous ----
    {
        float4* geo = reinterpret_cast<float4*>(out + (size_t)n_rays * 3 + (size_t)ray0 * 384);
        const float4 z = make_float4(0.f, 0.f, 0.f, 0.f);
        #pragma unroll
        for (int i = 0; i < 6; i++) geo[lane + i * 32] = z;
    }

    // ---- phase-1 deltas / densities ----
    float tn0 = __shfl_down_sync(0xffffffffu, tA0.x, 1);
    float tn1 = __shfl_down_sync(0xffffffffu, tA1.x, 1);
    if (lane == 31) { tn0 = t64_0; tn1 = t64_1; }
    float dd00 = sdf_density(dA0.x) * (tA0.y - tA0.x);
    float dd01 = sdf_density(dA0.y) * (tn0 - tA0.y);
    float dd10 = sdf_density(dA1.x) * (tA1.y - tA1.x);
    float dd11 = sdf_density(dA1.y) * (tn1 - tA1.y);

    // ---- fused dual warp scan (independent chains) ----
    float x0 = dd00 + dd01;
    float x1 = dd10 + dd11;
    #pragma unroll
    for (int off = 1; off < 32; off <<= 1) {
        float y0 = __shfl_up_sync(0xffffffffu, x0, off);
        float y1 = __shfl_up_sync(0xffffffffu, x1, off);
        if (lane >= off) { x0 += y0; x1 += y1; }
    }
    float excl0 = __shfl_up_sync(0xffffffffu, x0, 1);
    float excl1 = __shfl_up_sync(0xffffffffu, x1, 1);
    if (lane == 0) { excl0 = 0.0f; excl1 = 0.0f; }
    const float half0 = __shfl_sync(0xffffffffu, x0, 31);
    const float half1 = __shfl_sync(0xffffffffu, x1, 31);

    float r0 = 0.f, g0 = 0.f, bb0 = 0.f;
    float r1 = 0.f, g1 = 0.f, bb1 = 0.f;

    // ---- phase-1 color, ray0 (per-lane cull) ----
    if (excl0 < CULL_LOG) {
        const float2* cp = reinterpret_cast<const float2*>(color + (size_t)ray0 * 384) + lane * 3;
        const float2 f0 = cp[0];
        const float2 f1 = cp[1];
        const float2 f2 = cp[2];
        float T0 = __expf(-excl0);
        float a0 = __expf(-dd00);
        float a1 = __expf(-dd01);
        float T1 = T0 * a0;
        float w0 = (1.0f - a0) * T0;
        float w1 = (1.0f - a1) * T1;
        r0  = w0 * f0.x + w1 * f1.y;
        g0  = w0 * f0.y + w1 * f2.x;
        bb0 = w0 * f1.x + w1 * f2.y;
    }
    // ---- phase-1 color, ray1 ----
    if (excl1 < CULL_LOG) {
        const float2* cp = reinterpret_cast<const float2*>(color + (size_t)ray1 * 384) + lane * 3;
        const float2 f0 = cp[0];
        const float2 f1 = cp[1];
        const float2 f2 = cp[2];
        float T0 = __expf(-excl1);
        float a0 = __expf(-dd10);
        float a1 = __expf(-dd11);
        float T1 = T0 * a0;
        float w0 = (1.0f - a0) * T0;
        float w1 = (1.0f - a1) * T1;
        r1  = w0 * f0.x + w1 * f1.y;
        g1  = w0 * f0.y + w1 * f2.x;
        bb1 = w0 * f1.x + w1 * f2.y;
    }

    // ---- phase 2, ray0 (warp-uniform tail cull) ----
    if (half0 < CULL_LOG) {
        const float2 dB = reinterpret_cast<const float2*>(distance + b0 + 64)[lane];
        const float2 tB = reinterpret_cast<const float2*>(depth    + b0 + 64)[lane];
        float tnB = __shfl_down_sync(0xffffffffu, tB.x, 1);
        float dlt1 = (lane == 31) ? FAR_DELTA : (tnB - tB.y);
        float e0 = sdf_density(dB.x) * (tB.y - tB.x);
        float e1 = sdf_density(dB.y) * dlt1;
        float xb = e0 + e1;
        #pragma unroll
        for (int off = 1; off < 32; off <<= 1) {
            float y = __shfl_up_sync(0xffffffffu, xb, off);
            if (lane >= off) xb += y;
        }
        float exb = __shfl_up_sync(0xffffffffu, xb, 1);
        if (lane == 0) exb = 0.0f;
        float ex = half0 + exb;
        if (ex < CULL_LOG) {
            const float2* cp = reinterpret_cast<const float2*>(color + (size_t)ray0 * 384 + 192) + lane * 3;
            const float2 f0 = cp[0];
            const float2 f1 = cp[1];
            const float2 f2 = cp[2];
            float T0 = __expf(-ex);
            float a0 = __expf(-e0);
            float a1 = __expf(-e1);
            float T1 = T0 * a0;
            float w0 = (1.0f - a0) * T0;
            float w1 = (1.0f - a1) * T1;
            r0  += w0 * f0.x + w1 * f1.y;
            g0  += w0 * f0.y + w1 * f2.x;
            bb0 += w0 * f1.x + w1 * f2.y;
        }
    }
    // ---- phase 2, ray1 ----
    if (half1 < CULL_LOG) {
        const float2 dB = reinterpret_cast<const float2*>(distance + b1 + 64)[lane];
        const float2 tB = reinterpret_cast<const float2*>(depth    + b1 + 64)[lane];
        float tnB = __shfl_down_sync(0xffffffffu, tB.x, 1);
        float dlt1 = (lane == 31) ? FAR_DELTA : (tnB - tB.y);
        float e0 = sdf_density(dB.x) * (tB.y - tB.x);
        float e1 = sdf_density(dB.y) * dlt1;
        float xb = e0 + e1;
        #pragma unroll
        for (int off = 1; off < 32; off <<= 1) {
            float y = __shfl_up_sync(0xffffffffu, xb, off);
            if (lane >= off) xb += y;
        }
        float exb = __shfl_up_sync(0xffffffffu, xb, 1);
        if (lane == 0) exb = 0.0f;
        float ex = half1 + exb;
        if (ex < CULL_LOG) {
            const float2* cp = reinterpret_cast<const float2*>(color + (size_t)ray1 * 384 + 192) + lane * 3;
            const float2 f0 = cp[0];
            const float2 f1 = cp[1];
            const float2 f2 = cp[2];
            float T0 = __expf(-ex);
            float a0 = __expf(-e0);
            float a1 = __expf(-e1);
            float T1 = T0 * a0;
            float w0 = (1.0f - a0) * T0;
            float w1 = (1.0f - a1) * T1;
            r1  += w0 * f0.x + w1 * f1.y;
            g1  += w0 * f0.y + w1 * f2.x;
            bb1 += w0 * f1.x + w1 * f2.y;
        }
    }

    // ---- warp reductions (6 independent chains) ----
    #pragma unroll
    for (int off = 16; off >= 1; off >>= 1) {
        r0  += __shfl_xor_sync(0xffffffffu, r0,  off);
        g0  += __shfl_xor_sync(0xffffffffu, g0,  off);
        bb0 += __shfl_xor_sync(0xffffffffu, bb0, off);
        r1  += __shfl_xor_sync(0xffffffffu, r1,  off);
        g1  += __shfl_xor_sync(0xffffffffu, g1,  off);
        bb1 += __shfl_xor_sync(0xffffffffu, bb1, off);
    }

    if (lane == 0) {
        out[(size_t)ray0 * 3 + 0] = r0;
        out[(size_t)ray0 * 3 + 1] = g0;
        out[(size_t)ray0 * 3 + 2] = bb0;
    } else if (lane == 1) {
        out[(size_t)ray1 * 3 + 0] = r1;
        out[(size_t)ray1 * 3 + 1] = g1;
        out[(size_t)ray1 * 3 + 2] = bb1;
    }
}

extern "C" void kernel_launch(void* const* d_in, const int* in_sizes, int n_in,
                              void* d_out, int out_size)
{
    const float* distance = (const float*)d_in[0];
    const float* color    = (const float*)d_in[1];
    const float* depth    = (const float*)d_in[2];
    float* out = (float*)d_out;

    const int n_rays = in_sizes[0] / 128;   // R = 65536 (even)

    // two rays per warp; 256 threads = 8 warps = 16 rays per block
    const int rays_per_block = 16;
    const int blocks = (n_rays + rays_per_block - 1) / rays_per_block;
    volume_sdf_fused_kernel<<<blocks, 256>>>(distance, color, depth, out, n_rays);
}